// round 1
// baseline (speedup 1.0000x reference)
#include <cuda_runtime.h>

#define NN 50000
#define EE 800000
#define ETOT 850000   // EE + NN self loops
#define DIM 128       // 4 heads * 32
#define NEG 0.2f

// ---------------- scratch (device globals; no allocation allowed) ----------------
__device__ float g_xl[NN * DIM];      // source transform (both layers, reused)
__device__ float g_xr[NN * DIM];      // destination transform
__device__ float g_h1[NN * DIM];      // layer-1 output
__device__ float g_logits[ETOT * 4];  // per-edge per-head logits (later: exp values)
__device__ int   g_count[NN];
__device__ int   g_rowptr[NN + 1];
__device__ int   g_cursor[NN];
__device__ int   g_col[ETOT];         // CSR: edge ids grouped by dst

// ---------------- CSR build ----------------
__global__ void zero_counts_kernel() {
    int i = blockIdx.x * blockDim.x + threadIdx.x;
    if (i < NN) g_count[i] = 0;
}

__global__ void hist_kernel(const int* __restrict__ ei) {
    int e = blockIdx.x * blockDim.x + threadIdx.x;
    if (e >= ETOT) return;
    int dst = (e < EE) ? ei[EE + e] : (e - EE);
    atomicAdd(&g_count[dst], 1);
}

__global__ void scan_kernel() {
    const int T = 1024;
    const int CH = (NN + T - 1) / T;   // 49
    int t = threadIdx.x;
    int b = t * CH;
    int e = min(b + CH, NN);
    int s = 0;
    for (int i = b; i < e; i++) s += g_count[i];
    __shared__ int sh[T];
    sh[t] = s;
    __syncthreads();
    for (int off = 1; off < T; off <<= 1) {
        int v = (t >= off) ? sh[t - off] : 0;
        __syncthreads();
        sh[t] += v;
        __syncthreads();
    }
    int run = (t == 0) ? 0 : sh[t - 1];
    for (int i = b; i < e; i++) {
        int c = g_count[i];
        g_rowptr[i] = run;
        g_cursor[i] = run;
        run += c;
    }
    if (t == 0) g_rowptr[NN] = sh[T - 1];
}

__global__ void scatter_kernel(const int* __restrict__ ei) {
    int e = blockIdx.x * blockDim.x + threadIdx.x;
    if (e >= ETOT) return;
    int dst = (e < EE) ? ei[EE + e] : (e - EE);
    int p = atomicAdd(&g_cursor[dst], 1);
    g_col[p] = e;
}

// ---------------- GEMM: C[M x 128] = A[M x 128] @ W[128 x 128] ----------------
// 64x64 tile, 256 threads, 4x4 register tile, BK=32.
// a_sel: 0 -> A param (layer-1 input x), 1 -> g_h1
// out_sel: 0 -> g_xl, 1 -> g_xr
__global__ void __launch_bounds__(256) gemm128_kernel(
        const float* __restrict__ Ain, const float* __restrict__ W,
        int a_sel, int out_sel, int M) {
    const float* A = a_sel ? g_h1 : Ain;
    float* C = out_sel ? g_xr : g_xl;

    __shared__ float As[64][32];
    __shared__ float Bs[32][64];

    int tid = threadIdx.x;
    int tx = tid & 15;
    int ty = tid >> 4;
    int m0 = blockIdx.x * 64;
    int n0 = blockIdx.y * 64;

    float acc[4][4] = {};

    for (int k0 = 0; k0 < 128; k0 += 32) {
        // A tile: 64 rows x 32 k
        {
            int r = tid >> 3, kq = tid & 7;
            float4 v = make_float4(0.f, 0.f, 0.f, 0.f);
            if (m0 + r < M) v = *(const float4*)&A[(size_t)(m0 + r) * 128 + k0 + kq * 4];
            *(float4*)&As[r][kq * 4] = v;
            float4 v2 = make_float4(0.f, 0.f, 0.f, 0.f);
            if (m0 + r + 32 < M) v2 = *(const float4*)&A[(size_t)(m0 + r + 32) * 128 + k0 + kq * 4];
            *(float4*)&As[r + 32][kq * 4] = v2;
        }
        // W tile: 32 k x 64 cols
        {
            int kk = tid >> 4, c4 = tid & 15;
            *(float4*)&Bs[kk][c4 * 4] = *(const float4*)&W[(k0 + kk) * 128 + n0 + c4 * 4];
            *(float4*)&Bs[kk + 16][c4 * 4] = *(const float4*)&W[(k0 + kk + 16) * 128 + n0 + c4 * 4];
        }
        __syncthreads();
        #pragma unroll
        for (int k = 0; k < 32; k++) {
            float4 bv = *(const float4*)&Bs[k][tx * 4];
            float a0 = As[ty * 4 + 0][k];
            float a1 = As[ty * 4 + 1][k];
            float a2 = As[ty * 4 + 2][k];
            float a3 = As[ty * 4 + 3][k];
            acc[0][0] += a0 * bv.x; acc[0][1] += a0 * bv.y; acc[0][2] += a0 * bv.z; acc[0][3] += a0 * bv.w;
            acc[1][0] += a1 * bv.x; acc[1][1] += a1 * bv.y; acc[1][2] += a1 * bv.z; acc[1][3] += a1 * bv.w;
            acc[2][0] += a2 * bv.x; acc[2][1] += a2 * bv.y; acc[2][2] += a2 * bv.z; acc[2][3] += a2 * bv.w;
            acc[3][0] += a3 * bv.x; acc[3][1] += a3 * bv.y; acc[3][2] += a3 * bv.z; acc[3][3] += a3 * bv.w;
        }
        __syncthreads();
    }
    #pragma unroll
    for (int i = 0; i < 4; i++) {
        int m = m0 + ty * 4 + i;
        if (m < M) {
            float4 o = make_float4(acc[i][0], acc[i][1], acc[i][2], acc[i][3]);
            *(float4*)&C[(size_t)m * 128 + n0 + tx * 4] = o;
        }
    }
}

// ---------------- Edge logits: one warp per edge ----------------
// logits[e][h] = sum_c leaky(xl[src,h,c] + xr[dst,h,c]) * att[h,c]
__global__ void __launch_bounds__(256) logits_kernel(
        const int* __restrict__ ei, const float* __restrict__ att) {
    int gw = (blockIdx.x * blockDim.x + threadIdx.x) >> 5;
    int l = threadIdx.x & 31;
    if (gw >= ETOT) return;
    int src = (gw < EE) ? ei[gw] : gw - EE;
    int dst = (gw < EE) ? ei[EE + gw] : gw - EE;

    float4 a = ((const float4*)att)[l];
    float4 p = ((const float4*)g_xl)[(size_t)src * 32 + l];
    float4 q = ((const float4*)g_xr)[(size_t)dst * 32 + l];

    float ex = p.x + q.x, ey = p.y + q.y, ez = p.z + q.z, ew = p.w + q.w;
    ex = (ex > 0.f) ? ex : NEG * ex;
    ey = (ey > 0.f) ? ey : NEG * ey;
    ez = (ez > 0.f) ? ez : NEG * ez;
    ew = (ew > 0.f) ? ew : NEG * ew;
    float s = ex * a.x + ey * a.y + ez * a.z + ew * a.w;

    // reduce within each 8-lane group (one head per group)
    s += __shfl_xor_sync(0xffffffffu, s, 1, 8);
    s += __shfl_xor_sync(0xffffffffu, s, 2, 8);
    s += __shfl_xor_sync(0xffffffffu, s, 4, 8);
    if ((l & 7) == 0) g_logits[(size_t)gw * 4 + (l >> 3)] = s;
}

// ---------------- Softmax + aggregate: one warp per destination node ----------------
// mode 0: out = g_h1 = relu(agg + b)         (concat over heads, 128-wide)
// mode 1: out param = relu(mean_h(agg) + b)  (32-wide)
__global__ void __launch_bounds__(256) agg_kernel(
        const int* __restrict__ ei, const float* __restrict__ bias,
        float* __restrict__ outp, int mode) {
    int d = (blockIdx.x * blockDim.x + threadIdx.x) >> 5;
    int l = threadIdx.x & 31;
    if (d >= NN) return;
    int s0 = g_rowptr[d], s1 = g_rowptr[d + 1];

    // pass 1: per-head max over edges
    float4 mx = make_float4(-1e30f, -1e30f, -1e30f, -1e30f);
    for (int i = s0 + l; i < s1; i += 32) {
        float4 lg = ((const float4*)g_logits)[g_col[i]];
        mx.x = fmaxf(mx.x, lg.x); mx.y = fmaxf(mx.y, lg.y);
        mx.z = fmaxf(mx.z, lg.z); mx.w = fmaxf(mx.w, lg.w);
    }
    #pragma unroll
    for (int off = 16; off; off >>= 1) {
        mx.x = fmaxf(mx.x, __shfl_xor_sync(0xffffffffu, mx.x, off));
        mx.y = fmaxf(mx.y, __shfl_xor_sync(0xffffffffu, mx.y, off));
        mx.z = fmaxf(mx.z, __shfl_xor_sync(0xffffffffu, mx.z, off));
        mx.w = fmaxf(mx.w, __shfl_xor_sync(0xffffffffu, mx.w, off));
    }

    // pass 2: exp + per-head sum; store exp back into g_logits (this warp owns these edges)
    float4 se = make_float4(0.f, 0.f, 0.f, 0.f);
    for (int i = s0 + l; i < s1; i += 32) {
        int e = g_col[i];
        float4 lg = ((const float4*)g_logits)[e];
        float4 aa;
        aa.x = __expf(lg.x - mx.x); aa.y = __expf(lg.y - mx.y);
        aa.z = __expf(lg.z - mx.z); aa.w = __expf(lg.w - mx.w);
        ((float4*)g_logits)[e] = aa;
        se.x += aa.x; se.y += aa.y; se.z += aa.z; se.w += aa.w;
    }
    #pragma unroll
    for (int off = 16; off; off >>= 1) {
        se.x += __shfl_xor_sync(0xffffffffu, se.x, off);
        se.y += __shfl_xor_sync(0xffffffffu, se.y, off);
        se.z += __shfl_xor_sync(0xffffffffu, se.z, off);
        se.w += __shfl_xor_sync(0xffffffffu, se.w, off);
    }
    __syncwarp();   // order pass-2 global writes before pass-3 cross-lane reads

    int head = l >> 3;
    float dn = (head == 0) ? se.x : (head == 1) ? se.y : (head == 2) ? se.z : se.w;
    float invdn = 1.0f / dn;

    // pass 3: weighted aggregation; lane l owns feature dims [4l, 4l+4)
    float4 acc = make_float4(0.f, 0.f, 0.f, 0.f);
    for (int i = s0; i < s1; i++) {
        int e = g_col[i];
        int src = (e < EE) ? ei[e] : e - EE;
        float w = g_logits[(size_t)e * 4 + head] * invdn;
        float4 v = ((const float4*)g_xl)[(size_t)src * 32 + l];
        acc.x += v.x * w; acc.y += v.y * w; acc.z += v.z * w; acc.w += v.w * w;
    }

    if (mode == 0) {
        float4 b = ((const float4*)bias)[l];
        float4 o;
        o.x = fmaxf(acc.x + b.x, 0.f);
        o.y = fmaxf(acc.y + b.y, 0.f);
        o.z = fmaxf(acc.z + b.z, 0.f);
        o.w = fmaxf(acc.w + b.w, 0.f);
        ((float4*)g_h1)[(size_t)d * 32 + l] = o;
    } else {
        // mean over heads: sum lanes {l, l+8, l+16, l+24}
        acc.x += __shfl_xor_sync(0xffffffffu, acc.x, 8);
        acc.y += __shfl_xor_sync(0xffffffffu, acc.y, 8);
        acc.z += __shfl_xor_sync(0xffffffffu, acc.z, 8);
        acc.w += __shfl_xor_sync(0xffffffffu, acc.w, 8);
        acc.x += __shfl_xor_sync(0xffffffffu, acc.x, 16);
        acc.y += __shfl_xor_sync(0xffffffffu, acc.y, 16);
        acc.z += __shfl_xor_sync(0xffffffffu, acc.z, 16);
        acc.w += __shfl_xor_sync(0xffffffffu, acc.w, 16);
        if (l < 8) {
            float4 b = ((const float4*)bias)[l];
            float4 o;
            o.x = fmaxf(acc.x * 0.25f + b.x, 0.f);
            o.y = fmaxf(acc.y * 0.25f + b.y, 0.f);
            o.z = fmaxf(acc.z * 0.25f + b.z, 0.f);
            o.w = fmaxf(acc.w * 0.25f + b.w, 0.f);
            ((float4*)outp)[(size_t)d * 8 + l] = o;
        }
    }
}

// ---------------- launch ----------------
extern "C" void kernel_launch(void* const* d_in, const int* in_sizes, int n_in,
                              void* d_out, int out_size) {
    const float* x   = (const float*)d_in[0];
    const int*   ei  = (const int*)d_in[1];
    const float* Wl1 = (const float*)d_in[2];
    const float* Wr1 = (const float*)d_in[3];
    const float* att1 = (const float*)d_in[4];
    const float* b1  = (const float*)d_in[5];
    const float* Wl2 = (const float*)d_in[6];
    const float* Wr2 = (const float*)d_in[7];
    const float* att2 = (const float*)d_in[8];
    const float* b2  = (const float*)d_in[9];
    float* out = (float*)d_out;

    // CSR by destination (same for both layers)
    zero_counts_kernel<<<(NN + 255) / 256, 256>>>();
    hist_kernel<<<(ETOT + 255) / 256, 256>>>(ei);
    scan_kernel<<<1, 1024>>>();
    scatter_kernel<<<(ETOT + 255) / 256, 256>>>(ei);

    dim3 gg((NN + 63) / 64, 2);
    int logit_blocks = (int)(((long long)ETOT * 32 + 255) / 256);
    int agg_blocks = (NN * 32 + 255) / 256;

    // ---- layer 1 ----
    gemm128_kernel<<<gg, 256>>>(x, Wl1, 0, 0, NN);   // g_xl = x @ Wl1
    gemm128_kernel<<<gg, 256>>>(x, Wr1, 0, 1, NN);   // g_xr = x @ Wr1
    logits_kernel<<<logit_blocks, 256>>>(ei, att1);
    agg_kernel<<<agg_blocks, 256>>>(ei, b1, nullptr, 0);   // -> g_h1 (relu)

    // ---- layer 2 ----
    gemm128_kernel<<<gg, 256>>>(nullptr, Wl2, 1, 0, NN);   // g_xl = h1 @ Wl2
    gemm128_kernel<<<gg, 256>>>(nullptr, Wr2, 1, 1, NN);   // g_xr = h1 @ Wr2
    logits_kernel<<<logit_blocks, 256>>>(ei, att2);
    agg_kernel<<<agg_blocks, 256>>>(ei, b2, out, 1);       // -> d_out (relu of head-mean)
}